// round 14
// baseline (speedup 1.0000x reference)
#include <cuda_runtime.h>
#include <math.h>

// Quincunx lattice max pooling:
//   coset0, coset1: [B=4, C=32, H=512, W=512] fp32
//   out:            [2, B, C, H, W] fp32   (out0 then out1)
//
// out0[i,j] = max(c0[i,j], c0[i+1,j], c0[i,j+1], c0[i+1,j+1], c1[i,j])
// out1[i,j] = max(c1[i,j], c1[i+1,j], c1[i,j+1], c1[i+1,j+1], c0[i+1,j+1])
// OOB -> -inf.
//
// R13: R9's proven recipe (2-row unit, 128-bit loads, write-through stores,
// block 512) widened to 8 columns so stores are 256-bit (st.global.wt.v8
// -> STG.256): 12x LDG.128 in, 4x STG.256 out per thread. Exact grid, no
// bounds check; row-pair index p is warp-uniform so edge branches never
// diverge.

#define HH   512
#define WW   512
#define W8   64           // 8-col groups per row
#define PP   256          // row pairs per image
#define NEGINF __int_as_float(0xff800000)

#define STG256(p, s) asm volatile( \
    "st.global.wt.v8.f32 [%0], {%1,%2,%3,%4,%5,%6,%7,%8};" \
    :: "l"(p), "f"((s)[0]), "f"((s)[1]), "f"((s)[2]), "f"((s)[3]), \
       "f"((s)[4]), "f"((s)[5]), "f"((s)[6]), "f"((s)[7]) : "memory")

__global__ void __launch_bounds__(512)
lattice_pool_kernel(const float* __restrict__ c0,
                    const float* __restrict__ c1,
                    float* __restrict__ out0,
                    float* __restrict__ out1)
{
    int idx = blockIdx.x * 512 + threadIdx.x;

    int jv  = idx & (W8 - 1);           // 8-col group
    int p   = (idx >> 6) & (PP - 1);    // row pair (warp-uniform)
    long img = idx >> 14;               // (b,c) plane

    long base = img * (long)(HH * WW) + (long)(2 * p) * WW + (long)jv * 8;
    bool last_pair = (p == PP - 1);
    bool last_col  = (jv == W8 - 1);
    const float ni = NEGINF;

    // Rows 2p, 2p+1, 2p+2 of both cosets, 8 floats each via 2x float4.
    float A[3][8], B[3][8];
#pragma unroll
    for (int r = 0; r < 2; r++) {
        *(float4*)&A[r][0] = *(const float4*)(c0 + base + r * WW);
        *(float4*)&A[r][4] = *(const float4*)(c0 + base + r * WW + 4);
        *(float4*)&B[r][0] = *(const float4*)(c1 + base + r * WW);
        *(float4*)&B[r][4] = *(const float4*)(c1 + base + r * WW + 4);
    }
    if (!last_pair) {                    // warp-uniform branch
        *(float4*)&A[2][0] = *(const float4*)(c0 + base + 2 * WW);
        *(float4*)&A[2][4] = *(const float4*)(c0 + base + 2 * WW + 4);
        *(float4*)&B[2][0] = *(const float4*)(c1 + base + 2 * WW);
        *(float4*)&B[2][4] = *(const float4*)(c1 + base + 2 * WW + 4);
    } else {
#pragma unroll
        for (int k = 0; k < 8; k++) { A[2][k] = ni; B[2][k] = ni; }
    }

    // Horizontal tail (column 8*jv+8) = lane+1's element 0.
    const unsigned m = 0xffffffffu;
    float An[3], Bn[3];
#pragma unroll
    for (int r = 0; r < 3; r++) {
        An[r] = __shfl_down_sync(m, A[r][0], 1);
        Bn[r] = __shfl_down_sync(m, B[r][0], 1);
    }

    int lane = threadIdx.x & 31;
    if (lane == 31) {
        if (!last_col) {
            long e = base + 8;
            An[0] = __ldg(c0 + e);
            An[1] = __ldg(c0 + e + WW);
            Bn[0] = __ldg(c1 + e);
            Bn[1] = __ldg(c1 + e + WW);
            if (!last_pair) {
                An[2] = __ldg(c0 + e + 2 * WW);
                Bn[2] = __ldg(c1 + e + 2 * WW);
            } else {
                An[2] = ni; Bn[2] = ni;
            }
        } else {
#pragma unroll
            for (int r = 0; r < 3; r++) { An[r] = ni; Bn[r] = ni; }
        }
    }

    // Output rows r = 0,1 (global rows 2p+r), window rows (r, r+1).
#pragma unroll
    for (int r = 0; r < 2; r++) {
        float va[9], vb[9];
#pragma unroll
        for (int k = 0; k < 8; k++) {
            va[k] = fmaxf(A[r][k], A[r + 1][k]);
            vb[k] = fmaxf(B[r][k], B[r + 1][k]);
        }
        va[8] = fmaxf(An[r], An[r + 1]);
        vb[8] = fmaxf(Bn[r], Bn[r + 1]);

        float o0[8], o1[8];
#pragma unroll
        for (int k = 0; k < 8; k++) {
            o0[k] = fmaxf(fmaxf(va[k], va[k + 1]), B[r][k]);
            float adiag = (k < 7) ? A[r + 1][k + 1] : An[r + 1];
            o1[k] = fmaxf(fmaxf(vb[k], vb[k + 1]), adiag);
        }

        long ob = base + (long)r * WW;
        STG256(out0 + ob, o0);
        STG256(out1 + ob, o1);
    }
}

extern "C" void kernel_launch(void* const* d_in, const int* in_sizes, int n_in,
                              void* d_out, int out_size)
{
    const float* c0 = (const float*)d_in[0];
    const float* c1 = (const float*)d_in[1];
    long per_coset = in_sizes[0];              // floats per coset
    float* out0 = (float*)d_out;
    float* out1 = out0 + per_coset;

    // units of (2 rows x 8 cols): per_coset / 16 threads, exact multiple of 512
    int total = (int)(per_coset / 16);
    lattice_pool_kernel<<<total / 512, 512>>>(c0, c1, out0, out1);
}

// round 15
// speedup vs baseline: 1.0012x; 1.0012x over previous
#include <cuda_runtime.h>
#include <math.h>

// Quincunx lattice max pooling, shapes fixed by the problem:
//   coset0, coset1: [B=4, C=32, H=512, W=512] fp32
//   out:            [2, B, C, H, W] fp32   (out0 then out1)
//
// out0[i,j] = max(c0[i,j], c0[i+1,j], c0[i,j+1], c0[i+1,j+1], c1[i,j])
// out1[i,j] = max(c1[i,j], c1[i+1,j], c1[i,j+1], c1[i+1,j+1], c0[i+1,j+1])
// OOB -> -inf (ignored).
//
// R14 (final): R9 configuration — the best cell of the explored mechanism
// matrix: 2-row unit, 128-bit loads (optimal granularity; .256 regressed),
// shuffle horizontal tails with lane-31 predicated scalar loads, __stwt
// write-through stores, block=512 — with the now-dead bounds check removed
// (grid is exact: B*C*PP*W4 = 8192 * 512 threads).

#define HH   512
#define WW   512
#define W4   128          // float4 per row
#define PP   256          // row pairs per image
#define NEGINF __int_as_float(0xff800000)

__global__ void __launch_bounds__(512)
lattice_pool_kernel(const float4* __restrict__ c0,
                    const float4* __restrict__ c1,
                    float4* __restrict__ out0,
                    float4* __restrict__ out1)
{
    int idx = blockIdx.x * 512 + threadIdx.x;

    int jv  = idx & (W4 - 1);           // float4 column
    int p   = (idx >> 7) & (PP - 1);    // row-pair within image
    long img = idx >> 15;               // (b,c) plane index

    long base = img * (long)(HH * W4) + (long)(2 * p) * W4 + jv;
    bool last_pair = (p == PP - 1);
    bool last_col  = (jv == W4 - 1);
    const float ni = NEGINF;
    const float4 ni4 = make_float4(ni, ni, ni, ni);

    // Three input rows per coset: 2p, 2p+1, 2p+2
    float4 a0 = c0[base];
    float4 a1 = c0[base + W4];
    float4 b0 = c1[base];
    float4 b1 = c1[base + W4];
    float4 a2 = last_pair ? ni4 : c0[base + 2 * W4];
    float4 b2 = last_pair ? ni4 : c1[base + 2 * W4];

    // Horizontal tail (element at column 4*jv+4) via shuffle from lane+1.
    const unsigned m = 0xffffffffu;
    float a0n = __shfl_down_sync(m, a0.x, 1);
    float a1n = __shfl_down_sync(m, a1.x, 1);
    float a2n = __shfl_down_sync(m, a2.x, 1);
    float b0n = __shfl_down_sync(m, b0.x, 1);
    float b1n = __shfl_down_sync(m, b1.x, 1);
    float b2n = __shfl_down_sync(m, b2.x, 1);

    int lane = threadIdx.x & 31;
    if (lane == 31) {
        if (!last_col) {
            const float* c0s = (const float*)c0;
            const float* c1s = (const float*)c1;
            long e = base * 4 + 4;      // scalar idx of col 4*jv+4, row 2p
            a0n = __ldg(c0s + e);
            a1n = __ldg(c0s + e + WW);
            b0n = __ldg(c1s + e);
            b1n = __ldg(c1s + e + WW);
            if (!last_pair) {
                a2n = __ldg(c0s + e + 2 * WW);
                b2n = __ldg(c1s + e + 2 * WW);
            } else {
                a2n = ni; b2n = ni;
            }
        } else {
            a0n = a1n = a2n = b0n = b1n = b2n = ni;
        }
    }

    float4 r;
    // out0 row 2p: c0 2x2 + c1 same-site
    {
        float vx = fmaxf(a0.x, a1.x), vy = fmaxf(a0.y, a1.y);
        float vz = fmaxf(a0.z, a1.z), vw = fmaxf(a0.w, a1.w);
        float vn = fmaxf(a0n, a1n);
        r.x = fmaxf(fmaxf(vx, vy), b0.x);
        r.y = fmaxf(fmaxf(vy, vz), b0.y);
        r.z = fmaxf(fmaxf(vz, vw), b0.z);
        r.w = fmaxf(fmaxf(vw, vn), b0.w);
        __stwt(&out0[base], r);
    }
    // out1 row 2p: c1 2x2 + c0 down-right diagonal
    {
        float vx = fmaxf(b0.x, b1.x), vy = fmaxf(b0.y, b1.y);
        float vz = fmaxf(b0.z, b1.z), vw = fmaxf(b0.w, b1.w);
        float vn = fmaxf(b0n, b1n);
        r.x = fmaxf(fmaxf(vx, vy), a1.y);
        r.y = fmaxf(fmaxf(vy, vz), a1.z);
        r.z = fmaxf(fmaxf(vz, vw), a1.w);
        r.w = fmaxf(fmaxf(vw, vn), a1n);
        __stwt(&out1[base], r);
    }
    // out0 row 2p+1: c0 rows (2p+1,2p+2) + c1 row 2p+1
    {
        float vx = fmaxf(a1.x, a2.x), vy = fmaxf(a1.y, a2.y);
        float vz = fmaxf(a1.z, a2.z), vw = fmaxf(a1.w, a2.w);
        float vn = fmaxf(a1n, a2n);
        r.x = fmaxf(fmaxf(vx, vy), b1.x);
        r.y = fmaxf(fmaxf(vy, vz), b1.y);
        r.z = fmaxf(fmaxf(vz, vw), b1.z);
        r.w = fmaxf(fmaxf(vw, vn), b1.w);
        __stwt(&out0[base + W4], r);
    }
    // out1 row 2p+1: c1 rows (2p+1,2p+2) + c0 row 2p+2 diagonal
    {
        float vx = fmaxf(b1.x, b2.x), vy = fmaxf(b1.y, b2.y);
        float vz = fmaxf(b1.z, b2.z), vw = fmaxf(b1.w, b2.w);
        float vn = fmaxf(b1n, b2n);
        r.x = fmaxf(fmaxf(vx, vy), a2.y);
        r.y = fmaxf(fmaxf(vy, vz), a2.z);
        r.z = fmaxf(fmaxf(vz, vw), a2.w);
        r.w = fmaxf(fmaxf(vw, vn), a2n);
        __stwt(&out1[base + W4], r);
    }
}

extern "C" void kernel_launch(void* const* d_in, const int* in_sizes, int n_in,
                              void* d_out, int out_size)
{
    const float4* c0 = (const float4*)d_in[0];
    const float4* c1 = (const float4*)d_in[1];
    int per_coset4 = in_sizes[0] / 4;          // float4 per coset
    int total = per_coset4 / 2;                // 2-row units (exact multiple of 512)
    float4* out0 = (float4*)d_out;
    float4* out1 = out0 + per_coset4;

    lattice_pool_kernel<<<total / 512, 512>>>(c0, c1, out0, out1);
}

// round 16
// speedup vs baseline: 1.0211x; 1.0199x over previous
#include <cuda_runtime.h>
#include <math.h>

// Quincunx lattice max pooling, shapes fixed by the problem:
//   coset0, coset1: [B=4, C=32, H=512, W=512] fp32
//   out:            [2, B, C, H, W] fp32   (out0 then out1)
//
// out0[i,j] = max(c0[i,j], c0[i+1,j], c0[i,j+1], c0[i+1,j+1], c1[i,j])
// out1[i,j] = max(c1[i,j], c1[i+1,j], c1[i,j+1], c1[i+1,j+1], c0[i+1,j+1])
// OOB -> -inf (ignored).
//
// R15 (final): best-measured configuration — 2-row unit, 128-bit loads,
// shuffle horizontal tails (lane-31 predicated scalar loads), __stwt
// write-through stores — at block=256 (last unmeasured cell; finer CTA
// granularity for wave/die balancing). Exact grid, no bounds check.

#define HH   512
#define WW   512
#define W4   128          // float4 per row
#define PP   256          // row pairs per image
#define NEGINF __int_as_float(0xff800000)

__global__ void __launch_bounds__(256)
lattice_pool_kernel(const float4* __restrict__ c0,
                    const float4* __restrict__ c1,
                    float4* __restrict__ out0,
                    float4* __restrict__ out1)
{
    int idx = blockIdx.x * 256 + threadIdx.x;

    int jv  = idx & (W4 - 1);           // float4 column
    int p   = (idx >> 7) & (PP - 1);    // row-pair within image
    long img = idx >> 15;               // (b,c) plane index

    long base = img * (long)(HH * W4) + (long)(2 * p) * W4 + jv;
    bool last_pair = (p == PP - 1);
    bool last_col  = (jv == W4 - 1);
    const float ni = NEGINF;
    const float4 ni4 = make_float4(ni, ni, ni, ni);

    // Three input rows per coset: 2p, 2p+1, 2p+2
    float4 a0 = c0[base];
    float4 a1 = c0[base + W4];
    float4 b0 = c1[base];
    float4 b1 = c1[base + W4];
    float4 a2 = last_pair ? ni4 : c0[base + 2 * W4];
    float4 b2 = last_pair ? ni4 : c1[base + 2 * W4];

    // Horizontal tail (element at column 4*jv+4) via shuffle from lane+1.
    const unsigned m = 0xffffffffu;
    float a0n = __shfl_down_sync(m, a0.x, 1);
    float a1n = __shfl_down_sync(m, a1.x, 1);
    float a2n = __shfl_down_sync(m, a2.x, 1);
    float b0n = __shfl_down_sync(m, b0.x, 1);
    float b1n = __shfl_down_sync(m, b1.x, 1);
    float b2n = __shfl_down_sync(m, b2.x, 1);

    int lane = threadIdx.x & 31;
    if (lane == 31) {
        if (!last_col) {
            const float* c0s = (const float*)c0;
            const float* c1s = (const float*)c1;
            long e = base * 4 + 4;      // scalar idx of col 4*jv+4, row 2p
            a0n = __ldg(c0s + e);
            a1n = __ldg(c0s + e + WW);
            b0n = __ldg(c1s + e);
            b1n = __ldg(c1s + e + WW);
            if (!last_pair) {
                a2n = __ldg(c0s + e + 2 * WW);
                b2n = __ldg(c1s + e + 2 * WW);
            } else {
                a2n = ni; b2n = ni;
            }
        } else {
            a0n = a1n = a2n = b0n = b1n = b2n = ni;
        }
    }

    float4 r;
    // out0 row 2p: c0 2x2 + c1 same-site
    {
        float vx = fmaxf(a0.x, a1.x), vy = fmaxf(a0.y, a1.y);
        float vz = fmaxf(a0.z, a1.z), vw = fmaxf(a0.w, a1.w);
        float vn = fmaxf(a0n, a1n);
        r.x = fmaxf(fmaxf(vx, vy), b0.x);
        r.y = fmaxf(fmaxf(vy, vz), b0.y);
        r.z = fmaxf(fmaxf(vz, vw), b0.z);
        r.w = fmaxf(fmaxf(vw, vn), b0.w);
        __stwt(&out0[base], r);
    }
    // out1 row 2p: c1 2x2 + c0 down-right diagonal
    {
        float vx = fmaxf(b0.x, b1.x), vy = fmaxf(b0.y, b1.y);
        float vz = fmaxf(b0.z, b1.z), vw = fmaxf(b0.w, b1.w);
        float vn = fmaxf(b0n, b1n);
        r.x = fmaxf(fmaxf(vx, vy), a1.y);
        r.y = fmaxf(fmaxf(vy, vz), a1.z);
        r.z = fmaxf(fmaxf(vz, vw), a1.w);
        r.w = fmaxf(fmaxf(vw, vn), a1n);
        __stwt(&out1[base], r);
    }
    // out0 row 2p+1: c0 rows (2p+1,2p+2) + c1 row 2p+1
    {
        float vx = fmaxf(a1.x, a2.x), vy = fmaxf(a1.y, a2.y);
        float vz = fmaxf(a1.z, a2.z), vw = fmaxf(a1.w, a2.w);
        float vn = fmaxf(a1n, a2n);
        r.x = fmaxf(fmaxf(vx, vy), b1.x);
        r.y = fmaxf(fmaxf(vy, vz), b1.y);
        r.z = fmaxf(fmaxf(vz, vw), b1.z);
        r.w = fmaxf(fmaxf(vw, vn), b1.w);
        __stwt(&out0[base + W4], r);
    }
    // out1 row 2p+1: c1 rows (2p+1,2p+2) + c0 row 2p+2 diagonal
    {
        float vx = fmaxf(b1.x, b2.x), vy = fmaxf(b1.y, b2.y);
        float vz = fmaxf(b1.z, b2.z), vw = fmaxf(b1.w, b2.w);
        float vn = fmaxf(b1n, b2n);
        r.x = fmaxf(fmaxf(vx, vy), a2.y);
        r.y = fmaxf(fmaxf(vy, vz), a2.z);
        r.z = fmaxf(fmaxf(vz, vw), a2.w);
        r.w = fmaxf(fmaxf(vw, vn), a2n);
        __stwt(&out1[base + W4], r);
    }
}

extern "C" void kernel_launch(void* const* d_in, const int* in_sizes, int n_in,
                              void* d_out, int out_size)
{
    const float4* c0 = (const float4*)d_in[0];
    const float4* c1 = (const float4*)d_in[1];
    int per_coset4 = in_sizes[0] / 4;          // float4 per coset
    int total = per_coset4 / 2;                // 2-row units (exact multiple of 256)
    float4* out0 = (float4*)d_out;
    float4* out1 = out0 + per_coset4;

    lattice_pool_kernel<<<total / 256, 256>>>(c0, c1, out0, out1);
}